// round 7
// baseline (speedup 1.0000x reference)
#include <cuda_runtime.h>

#define N_NODES 100000
#define E_EDGES 1600000
#define FIN  16
#define FMID 32
#define FOUT 16

#define CHUNK   512
#define NCHUNK  ((N_NODES + CHUNK - 1) / CHUNK)   // 196

// ---------------- device scratch ----------------
__device__ int   g_cnt[N_NODES];          // histogram of col (statically 0; reset each replay)
__device__ int   g_start[N_NODES];        // CSC segment starts
__device__ int   g_cursor[N_NODES];       // place cursor; == segment end after k_place
__device__ int   g_srow[E_EDGES];         // rows sorted by col
__device__ int   g_bsum[NCHUNK];          // scan block sums
__device__ float g_dinv[N_NODES];
__device__ float g_h1s[N_NODES * FMID];   // (x @ W1) * dinv
__device__ float g_u1 [N_NODES * FMID];   // neighbor sum (incl self)
__device__ float g_h2s[N_NODES * FOUT];
__device__ float g_u2 [N_NODES * FOUT];
__device__ int   g_is64;

// ---------------- kernels ----------------

// Detect int64 vs int32 edge storage (odd 32-bit words all zero <=> int64).
__global__ void k_detect(const unsigned int* __restrict__ words) {
    __shared__ unsigned int s_or;
    if (threadIdx.x == 0) s_or = 0u;
    __syncthreads();
    unsigned int acc = 0u;
    for (int j = threadIdx.x; j < 8192; j += blockDim.x)
        acc |= words[2 * j + 1];
    atomicOr(&s_or, acc);
    __syncthreads();
    if (threadIdx.x == 0) g_is64 = (s_or == 0u) ? 1 : 0;
}

__device__ __forceinline__ int load_idx(const void* p, int i) {
    return g_is64 ? (int)((const long long*)p)[i] : ((const int*)p)[i];
}

// Histogram over col (second half of edge_index).
__global__ void k_hist(const void* __restrict__ edge_raw, int E) {
    int e = blockIdx.x * blockDim.x + threadIdx.x;
    if (e >= E) return;
    atomicAdd(&g_cnt[load_idx(edge_raw, E + e)], 1);
}

// Scan phase A: per-chunk totals.
__global__ void k_scanA() {
    __shared__ int sh[CHUNK];
    int i = blockIdx.x * CHUNK + threadIdx.x;
    sh[threadIdx.x] = (i < N_NODES) ? g_cnt[i] : 0;
    __syncthreads();
    for (int s = CHUNK / 2; s > 0; s >>= 1) {
        if (threadIdx.x < s) sh[threadIdx.x] += sh[threadIdx.x + s];
        __syncthreads();
    }
    if (threadIdx.x == 0) g_bsum[blockIdx.x] = sh[0];
}

// Scan phase B: exclusive scan of NCHUNK chunk totals (1 block).
__global__ void k_scanB() {
    __shared__ int sh[NCHUNK];
    if (threadIdx.x < NCHUNK) sh[threadIdx.x] = g_bsum[threadIdx.x];
    __syncthreads();
    if (threadIdx.x == 0) {
        int run = 0;
        for (int j = 0; j < NCHUNK; j++) { int v = sh[j]; sh[j] = run; run += v; }
    }
    __syncthreads();
    if (threadIdx.x < NCHUNK) g_bsum[threadIdx.x] = sh[threadIdx.x];
}

// Scan phase C: in-chunk exclusive scan + chunk offset; also dinv and cnt reset.
__global__ void k_scanC() {
    __shared__ int sh[CHUNK];
    int i = blockIdx.x * CHUNK + threadIdx.x;
    int v = (i < N_NODES) ? g_cnt[i] : 0;
    sh[threadIdx.x] = v;
    __syncthreads();
    // Hillis-Steele inclusive scan
    for (int s = 1; s < CHUNK; s <<= 1) {
        int add = (threadIdx.x >= s) ? sh[threadIdx.x - s] : 0;
        __syncthreads();
        sh[threadIdx.x] += add;
        __syncthreads();
    }
    if (i < N_NODES) {
        int start = g_bsum[blockIdx.x] + sh[threadIdx.x] - v;  // exclusive
        g_start[i]  = start;
        g_cursor[i] = start;
        g_dinv[i]   = rsqrtf((float)(v + 1));                  // +1 self-loop
        g_cnt[i]    = 0;                                       // reset for next replay
    }
}

// Place rows into col-sorted order.
__global__ void k_place(const void* __restrict__ edge_raw, int E) {
    int e = blockIdx.x * blockDim.x + threadIdx.x;
    if (e >= E) return;
    int r = load_idx(edge_raw, e);
    int c = load_idx(edge_raw, E + e);
    int p = atomicAdd(&g_cursor[c], 1);
    g_srow[p] = r;
}

// h1s = (x @ W1) * dinv.  32 threads per node (one warp).
__global__ void k_lin1(const float* __restrict__ x,
                       const float* __restrict__ W1) {
    __shared__ float sW[FIN * FMID];
    for (int t = threadIdx.x; t < FIN * FMID; t += blockDim.x) sW[t] = W1[t];
    __syncthreads();
    int idx = blockIdx.x * blockDim.x + threadIdx.x;
    if (idx >= N_NODES * FMID) return;
    int i = idx >> 5;
    int f = idx & 31;
    float d = g_dinv[i];
    float acc = 0.0f;
    #pragma unroll
    for (int k = 0; k < FIN; k++)
        acc = fmaf(x[i * FIN + k], sW[k * FMID + f], acc);
    g_h1s[idx] = acc * d;
}

// Layer-1 gather: warp per node, lane = feature. u1 = self + sum(neighbors).
__global__ void k_gather1() {
    int w = (blockIdx.x * blockDim.x + threadIdx.x) >> 5;
    if (w >= N_NODES) return;
    int f = threadIdx.x & 31;
    int j = g_start[w];
    int epos = g_cursor[w];                 // end (cursor advanced by place)
    float acc = g_h1s[w * FMID + f];        // self-loop term
    for (; j + 4 <= epos; j += 4) {
        int r0 = g_srow[j], r1 = g_srow[j+1], r2 = g_srow[j+2], r3 = g_srow[j+3];
        float a0 = g_h1s[r0 * FMID + f];
        float a1 = g_h1s[r1 * FMID + f];
        float a2 = g_h1s[r2 * FMID + f];
        float a3 = g_h1s[r3 * FMID + f];
        acc += (a0 + a1) + (a2 + a3);
    }
    for (; j < epos; j++)
        acc += g_h1s[g_srow[j] * FMID + f];
    g_u1[w * FMID + f] = acc;
}

// o1 = relu(dinv*u1 + b1) ; h2s = (o1 @ W2) * dinv.  16 threads per node.
__global__ void k_lin2(const float* __restrict__ W2,
                       const float* __restrict__ b1) {
    __shared__ float sW[FMID * FOUT];
    __shared__ float sb[FMID];
    for (int t = threadIdx.x; t < FMID * FOUT; t += blockDim.x) sW[t] = W2[t];
    for (int t = threadIdx.x; t < FMID; t += blockDim.x) sb[t] = b1[t];
    __syncthreads();
    int idx = blockIdx.x * blockDim.x + threadIdx.x;
    if (idx >= N_NODES * FOUT) return;
    int i = idx >> 4;
    int f = idx & 15;
    float d = g_dinv[i];
    float acc = 0.0f;
    #pragma unroll
    for (int k = 0; k < FMID; k++) {
        float v = fmaxf(fmaf(g_u1[i * FMID + k], d, sb[k]), 0.0f);
        acc = fmaf(v, sW[k * FOUT + f], acc);
    }
    g_h2s[idx] = acc * d;
}

// Layer-2 gather: half-warp per node, lane = feature (16).
__global__ void k_gather2() {
    int h = (blockIdx.x * blockDim.x + threadIdx.x) >> 4;
    if (h >= N_NODES) return;
    int f = threadIdx.x & 15;
    int j = g_start[h];
    int epos = g_cursor[h];
    float acc = g_h2s[h * FOUT + f];
    for (; j + 4 <= epos; j += 4) {
        int r0 = g_srow[j], r1 = g_srow[j+1], r2 = g_srow[j+2], r3 = g_srow[j+3];
        float a0 = g_h2s[r0 * FOUT + f];
        float a1 = g_h2s[r1 * FOUT + f];
        float a2 = g_h2s[r2 * FOUT + f];
        float a3 = g_h2s[r3 * FOUT + f];
        acc += (a0 + a1) + (a2 + a3);
    }
    for (; j < epos; j++)
        acc += g_h2s[g_srow[j] * FOUT + f];
    g_u2[h * FOUT + f] = acc;
}

// out = relu(dinv*u2 + b2) @ fc_W + fc_b
__global__ void k_final(const float* __restrict__ fcW,
                        const float* __restrict__ fcb,
                        const float* __restrict__ b2,
                        float* __restrict__ out) {
    int i = blockIdx.x * blockDim.x + threadIdx.x;
    if (i >= N_NODES) return;
    float d = g_dinv[i];
    float acc = __ldg(&fcb[0]);
    #pragma unroll
    for (int k = 0; k < FOUT; k++) {
        float v = fmaxf(fmaf(g_u2[i * FOUT + k], d, __ldg(&b2[k])), 0.0f);
        acc = fmaf(v, __ldg(&fcW[k]), acc);
    }
    out[i] = acc;
}

// ---------------- launch ----------------
extern "C" void kernel_launch(void* const* d_in, const int* in_sizes, int n_in,
                              void* d_out, int out_size) {
    const void*  edge = d_in[0];
    const float* x    = (const float*)d_in[1];
    const float* W1   = (const float*)d_in[2];
    const float* b1   = (const float*)d_in[3];
    const float* W2   = (const float*)d_in[4];
    const float* b2   = (const float*)d_in[5];
    const float* fcW  = (const float*)d_in[6];
    const float* fcb  = (const float*)d_in[7];
    float* out = (float*)d_out;

    const int E = in_sizes[0] / 2;
    const int T = 256;

    k_detect<<<1, 256>>>((const unsigned int*)edge);
    k_hist  <<<(E + T - 1) / T, T>>>(edge, E);
    k_scanA <<<NCHUNK, CHUNK>>>();
    k_scanB <<<1, 256>>>();
    k_scanC <<<NCHUNK, CHUNK>>>();
    k_place <<<(E + T - 1) / T, T>>>(edge, E);
    k_lin1  <<<(N_NODES * FMID + T - 1) / T, T>>>(x, W1);
    k_gather1<<<(N_NODES * 32 + T - 1) / T, T>>>();
    k_lin2  <<<(N_NODES * FOUT + T - 1) / T, T>>>(W2, b1);
    k_gather2<<<(N_NODES * 16 + T - 1) / T, T>>>();
    k_final <<<(N_NODES + T - 1) / T, T>>>(fcW, fcb, b2, out);
}

// round 8
// speedup vs baseline: 1.0899x; 1.0899x over previous
#include <cuda_runtime.h>

#define N_NODES 100000
#define E_EDGES 1600000
#define FIN  16
#define FMID 32
#define FOUT 16

#define CHUNK   512
#define NCHUNK  ((N_NODES + CHUNK - 1) / CHUNK)   // 196

// ---------------- device scratch ----------------
__device__ int   g_cnt[N_NODES];          // col histogram (0 at start of each replay)
__device__ int   g_start[N_NODES];        // CSC segment starts
__device__ int   g_cursor[N_NODES];       // place cursor; == segment end after k_place
__device__ int   g_srow[E_EDGES];         // rows sorted by col
__device__ int   g_bsum[NCHUNK];          // per-chunk totals
__device__ float g_dinv[N_NODES];
__device__ float g_h1s[N_NODES * FMID];   // (x @ W1) * dinv
__device__ float g_h2s[N_NODES * FOUT];   // (relu(o1) @ W2) * dinv
__device__ int   g_is64;

// ---------------- kernels ----------------

// Fused dtype-detect + col histogram.
// Every block samples the SAME 512 odd words -> identical is64 decision.
__global__ void k_hist(const unsigned int* __restrict__ words,
                       const void* __restrict__ edge_raw, int E) {
    __shared__ unsigned int s_or;
    if (threadIdx.x == 0) s_or = 0u;
    __syncthreads();
    unsigned int acc = words[2 * threadIdx.x + 1] | words[2 * (threadIdx.x + 256) + 1];
    // warp-OR then one atomic per warp
    #pragma unroll
    for (int s = 16; s > 0; s >>= 1)
        acc |= __shfl_xor_sync(0xffffffffu, acc, s);
    if ((threadIdx.x & 31) == 0) atomicOr(&s_or, acc);
    __syncthreads();
    const int is64 = (s_or == 0u) ? 1 : 0;
    if (blockIdx.x == 0 && threadIdx.x == 0) g_is64 = is64;

    int e = blockIdx.x * blockDim.x + threadIdx.x;
    if (e >= E) return;
    int c = is64 ? (int)((const long long*)edge_raw)[E + e]
                 : ((const int*)edge_raw)[E + e];
    atomicAdd(&g_cnt[c], 1);
}

// Per-chunk totals.
__global__ void k_scanA() {
    __shared__ int sh[CHUNK];
    int i = blockIdx.x * CHUNK + threadIdx.x;
    sh[threadIdx.x] = (i < N_NODES) ? g_cnt[i] : 0;
    __syncthreads();
    for (int s = CHUNK / 2; s > 0; s >>= 1) {
        if (threadIdx.x < s) sh[threadIdx.x] += sh[threadIdx.x + s];
        __syncthreads();
    }
    if (threadIdx.x == 0) g_bsum[blockIdx.x] = sh[0];
}

// Fused: chunk-offset reduction (old scanB) + in-chunk scan + dinv + cnt reset
// + lin1 (h1s = (x@W1)*dinv) for this block's 512 nodes.
__global__ void k_scanC_lin1(const float* __restrict__ x,
                             const float* __restrict__ W1) {
    __shared__ int   sh[CHUNK];
    __shared__ float sdinv[CHUNK];
    __shared__ float sW[FIN * FMID];
    __shared__ int   soff[CHUNK];

    // exclusive chunk offset: sum of bsum[t] for t < blockIdx.x
    soff[threadIdx.x] = (threadIdx.x < blockIdx.x && threadIdx.x < NCHUNK)
                        ? g_bsum[threadIdx.x] : 0;
    for (int t = threadIdx.x; t < FIN * FMID; t += blockDim.x) sW[t] = W1[t];

    int i = blockIdx.x * CHUNK + threadIdx.x;
    int v = (i < N_NODES) ? g_cnt[i] : 0;
    sh[threadIdx.x] = v;
    __syncthreads();
    for (int s = CHUNK / 2; s > 0; s >>= 1) {
        if (threadIdx.x < s) soff[threadIdx.x] += soff[threadIdx.x + s];
        __syncthreads();
    }
    int chunk_off = soff[0];
    // Hillis-Steele inclusive scan of sh
    for (int s = 1; s < CHUNK; s <<= 1) {
        int add = (threadIdx.x >= s) ? sh[threadIdx.x - s] : 0;
        __syncthreads();
        sh[threadIdx.x] += add;
        __syncthreads();
    }
    float d = rsqrtf((float)(v + 1));
    sdinv[threadIdx.x] = d;
    if (i < N_NODES) {
        int start = chunk_off + sh[threadIdx.x] - v;   // exclusive
        g_start[i]  = start;
        g_cursor[i] = start;
        g_dinv[i]   = d;
        g_cnt[i]    = 0;                               // ready for next replay
    }
    __syncthreads();

    // lin1 for this block's nodes: 512 threads x 32 iters = 512 nodes x 32 features
    int node_base = blockIdx.x * CHUNK;
    int nloc_count = min(CHUNK, N_NODES - node_base);
    for (int t = threadIdx.x; t < nloc_count * FMID; t += blockDim.x) {
        int nl = t >> 5;
        int f  = t & 31;
        int n  = node_base + nl;
        float acc = 0.0f;
        #pragma unroll
        for (int k = 0; k < FIN; k++)
            acc = fmaf(__ldg(&x[n * FIN + k]), sW[k * FMID + f], acc);
        g_h1s[n * FMID + f] = acc * sdinv[nl];
    }
}

// Place rows into col-sorted order.
__global__ void k_place(const void* __restrict__ edge_raw, int E) {
    int e = blockIdx.x * blockDim.x + threadIdx.x;
    if (e >= E) return;
    int r, c;
    if (g_is64) {
        const long long* p = (const long long*)edge_raw;
        r = (int)p[e];  c = (int)p[E + e];
    } else {
        const int* p = (const int*)edge_raw;
        r = p[e];       c = p[E + e];
    }
    int pidx = atomicAdd(&g_cursor[c], 1);
    g_srow[pidx] = r;
}

// Fused gather1 + lin2. Warp per node, lane = feature (32).
// u1 stays in registers; o1 staged in shared; lanes 0..15 do the 32x16 matmul.
__global__ void k_gather1_lin2(const float* __restrict__ W2,
                               const float* __restrict__ b1) {
    __shared__ float sW[FMID * FOUT];
    __shared__ float sb[FMID];
    __shared__ float so1[8][FMID];          // 8 warps per 256-thread block
    for (int t = threadIdx.x; t < FMID * FOUT; t += blockDim.x) sW[t] = W2[t];
    for (int t = threadIdx.x; t < FMID; t += blockDim.x) sb[t] = b1[t];
    __syncthreads();

    int w = (blockIdx.x * blockDim.x + threadIdx.x) >> 5;
    if (w >= N_NODES) return;
    int f  = threadIdx.x & 31;
    int wl = (threadIdx.x >> 5) & 7;

    int j    = g_start[w];
    int epos = g_cursor[w];
    float acc = g_h1s[w * FMID + f];        // self-loop
    for (; j + 4 <= epos; j += 4) {
        int r0 = g_srow[j], r1 = g_srow[j+1], r2 = g_srow[j+2], r3 = g_srow[j+3];
        float a0 = g_h1s[r0 * FMID + f];
        float a1 = g_h1s[r1 * FMID + f];
        float a2 = g_h1s[r2 * FMID + f];
        float a3 = g_h1s[r3 * FMID + f];
        acc += (a0 + a1) + (a2 + a3);
    }
    for (; j < epos; j++)
        acc += g_h1s[g_srow[j] * FMID + f];

    float d = g_dinv[w];
    so1[wl][f] = fmaxf(fmaf(acc, d, sb[f]), 0.0f);   // o1 (post-relu)
    __syncwarp();
    if (f < FOUT) {
        float s = 0.0f;
        #pragma unroll
        for (int k = 0; k < FMID; k++)
            s = fmaf(so1[wl][k], sW[k * FOUT + f], s);
        g_h2s[w * FOUT + f] = s * d;
    }
}

// Fused gather2 + final. Half-warp per node, lane = feature (16),
// then shuffle-reduce the 16-lane dot with fc_W.
__global__ void k_gather2_final(const float* __restrict__ fcW,
                                const float* __restrict__ fcb,
                                const float* __restrict__ b2,
                                float* __restrict__ out) {
    int h = (blockIdx.x * blockDim.x + threadIdx.x) >> 4;
    if (h >= N_NODES) return;
    int f = threadIdx.x & 15;

    int j    = g_start[h];
    int epos = g_cursor[h];
    float acc = g_h2s[h * FOUT + f];        // self-loop
    for (; j + 4 <= epos; j += 4) {
        int r0 = g_srow[j], r1 = g_srow[j+1], r2 = g_srow[j+2], r3 = g_srow[j+3];
        float a0 = g_h2s[r0 * FOUT + f];
        float a1 = g_h2s[r1 * FOUT + f];
        float a2 = g_h2s[r2 * FOUT + f];
        float a3 = g_h2s[r3 * FOUT + f];
        acc += (a0 + a1) + (a2 + a3);
    }
    for (; j < epos; j++)
        acc += g_h2s[g_srow[j] * FOUT + f];

    float d = g_dinv[h];
    float v = fmaxf(fmaf(acc, d, __ldg(&b2[f])), 0.0f) * __ldg(&fcW[f]);
    // reduce 16 lanes (stay within the half-warp via width=16)
    #pragma unroll
    for (int s = 8; s > 0; s >>= 1)
        v += __shfl_xor_sync(0xffffffffu, v, s, 16);
    if (f == 0) out[h] = v + __ldg(&fcb[0]);
}

// ---------------- launch ----------------
extern "C" void kernel_launch(void* const* d_in, const int* in_sizes, int n_in,
                              void* d_out, int out_size) {
    const void*  edge = d_in[0];
    const float* x    = (const float*)d_in[1];
    const float* W1   = (const float*)d_in[2];
    const float* b1   = (const float*)d_in[3];
    const float* W2   = (const float*)d_in[4];
    const float* b2   = (const float*)d_in[5];
    const float* fcW  = (const float*)d_in[6];
    const float* fcb  = (const float*)d_in[7];
    float* out = (float*)d_out;

    const int E = in_sizes[0] / 2;
    const int T = 256;

    k_hist        <<<(E + T - 1) / T, T>>>((const unsigned int*)edge, edge, E);
    k_scanA       <<<NCHUNK, CHUNK>>>();
    k_scanC_lin1  <<<NCHUNK, CHUNK>>>(x, W1);
    k_place       <<<(E + T - 1) / T, T>>>(edge, E);
    k_gather1_lin2<<<(N_NODES * 32 + T - 1) / T, T>>>(W2, b1);
    k_gather2_final<<<(N_NODES * 16 + T - 1) / T, T>>>(fcW, fcb, b2, out);
}